// round 4
// baseline (speedup 1.0000x reference)
#include <cuda_runtime.h>
#include <cuda_bf16.h>
#include <math.h>

#define BATCH   16384
#define CCH     72
#define HH      34
#define SAMP    (CCH*HH)      /* 2448 */
#define OUTC    84
#define OSAMP   (OUTC*HH)     /* 2856 */
#define TB      8             /* samples per conv block */
#define BT      136           /* conv block threads = TB * 17 */
#define RED_BLOCKS 64
#define RED_PER    256
#define BN_COUNT   (16384.0f*34.0f)
#define BN_EPS_F   1e-5f

__device__ float g_mult[BATCH*6];
__device__ float g_part[BATCH*144];
__device__ float g_part2[RED_BLOCKS*144];
__device__ float g_ss[144];

__device__ __forceinline__ float sigmoidf_(float z) {
    return 1.0f / (1.0f + __expf(-z));
}

#define FMA2(d, a, b, c) \
    asm("fma.rn.f32x2 %0, %1, %2, %3;" : "=l"(d) : "l"(a), "l"(b), "l"(c))
#define PACK2(p, v) do { unsigned int _b = __float_as_uint(v); \
    asm("mov.b64 %0, {%1, %1};" : "=l"(p) : "r"(_b)); } while (0)
#define UNPACK2(lo, hi, p) do { unsigned int _l, _h; \
    asm("mov.b64 {%0, %1}, %2;" : "=r"(_l), "=r"(_h) : "l"(p)); \
    lo = __uint_as_float(_l); hi = __uint_as_float(_h); } while (0)

// ---------------------------------------------------------------------------
// K1: per-sample gates + BN partial sums + copy x into output channels [0,72)
// ---------------------------------------------------------------------------
__global__ void __launch_bounds__(128) k1_stats(
    const float* __restrict__ x,
    const float* __restrict__ fcw,
    const float* __restrict__ fcb,
    float* __restrict__ out)
{
    __shared__ float xs[SAMP];
    __shared__ float ws[HH];
    __shared__ float s1[CCH], s2[CCH], sw[CCH];
    __shared__ float lin[6];

    const int b   = blockIdx.x;
    const int tid = threadIdx.x;

    const float4* xin4 = (const float4*)(x + (size_t)b * SAMP);
    float4*       out4 = (float4*)(out + (size_t)b * OSAMP);
    float4*       xs4  = (float4*)xs;
    #pragma unroll
    for (int i = tid; i < SAMP/4; i += 128) {
        float4 v = xin4[i];
        xs4[i]  = v;
        out4[i] = v;
    }
    if (tid < HH) ws[tid] = fcw[tid];
    __syncthreads();

    if (tid < CCH) {
        float a1 = 0.f, a2 = 0.f, aw = 0.f;
        const float* row = xs + tid * HH;
        #pragma unroll
        for (int h = 0; h < HH; h++) {
            float v = row[h];
            a1 += v; a2 += v * v; aw += v * ws[h];
        }
        s1[tid] = a1; s2[tid] = a2; sw[tid] = aw;
    }
    __syncthreads();

    if (tid < 6) {
        float s = 0.f;
        #pragma unroll
        for (int c = 0; c < 12; c++) s += sw[tid * 12 + c];
        lin[tid] = s * (1.0f/12.0f) + fcb[0];
    }
    __syncthreads();

    if (tid < CCH) {
        const int cls = tid / 12;
        float mult;
        if (cls == 0)       mult = sigmoidf_(lin[5] + lin[0]);
        else if (cls == 5)  mult = 1.0f;
        else                mult = sigmoidf_(lin[5 - cls] + lin[5]);
        int src;
        if (cls == 0 || cls == 5) src = tid;
        else                      src = tid + 12 * (5 - 2 * cls);

        g_part[(size_t)b * 144 + tid * 2 + 0] = mult * s1[src];
        g_part[(size_t)b * 144 + tid * 2 + 1] = mult * mult * s2[src];
        if ((tid % 12) == 0) g_mult[b * 6 + cls] = mult;
    }
}

// ---------------------------------------------------------------------------
// K2 / K2b: deterministic BN stat reduction
// ---------------------------------------------------------------------------
__global__ void __launch_bounds__(144) k2_reduce()
{
    const int t   = threadIdx.x;
    const int blk = blockIdx.x;
    float acc = 0.f;
    size_t base = (size_t)blk * RED_PER * 144 + t;
    #pragma unroll 8
    for (int i = 0; i < RED_PER; i++) acc += g_part[base + (size_t)i * 144];
    g_part2[blk * 144 + t] = acc;
}

__global__ void __launch_bounds__(72) k2b_final(
    const float* __restrict__ gamma,
    const float* __restrict__ beta)
{
    const int c = threadIdx.x;
    float s = 0.f, q = 0.f;
    #pragma unroll 8
    for (int i = 0; i < RED_BLOCKS; i++) {
        s += g_part2[i * 144 + 2 * c + 0];
        q += g_part2[i * 144 + 2 * c + 1];
    }
    const float inv = 1.0f / BN_COUNT;
    float mu    = s * inv;
    float var   = q * inv - mu * mu;
    float scale = gamma[c] * rsqrtf(var + BN_EPS_F);
    g_ss[c]      = scale;
    g_ss[72 + c] = beta[c] - mu * scale;
}

// ---------------------------------------------------------------------------
// K3: xxx -> BN -> relu (bf16 in smem) -> 3-tap conv, FFMA2, 2 h per thread
// block = 136 threads = 8 samples x 17 h-pairs; 4 blocks/SM
// ---------------------------------------------------------------------------
__global__ void __launch_bounds__(BT, 4) k3_conv(
    const float* __restrict__ x,
    const float* __restrict__ convw,
    float* __restrict__ out)
{
    extern __shared__ float sm[];
    float*          wsm  = sm;                                   // 2592 f
    __nv_bfloat16*  hp   = (__nv_bfloat16*)(wsm + 2592);         // TB*2592 bf16
    float*          Asl  = (float*)(hp + TB * 2592);             // TB*72
    float*          Bc   = Asl + TB * 72;                        // 72
    int*            offc = (int*)(Bc + 72);                      // 72
    float*          scx  = (float*)(offc + 72);                  // 72
    float*          mlsh = scx + 72;                             // TB*6

    const int tid = threadIdx.x;
    const int b0  = blockIdx.x * TB;

    // weights -> smem, [(ic*3+k)*12 + oc]
    for (int i = tid; i < 2592; i += BT) {
        int oc = i % 12;
        int k  = (i / 12) % 3;
        int ic = i / 36;
        wsm[i] = convw[oc * 216 + ic * 3 + k];
    }
    if (tid < 72) {
        int g = tid / 12, r = tid - g * 12;
        int xcls = (g == 0 || g == 5) ? g : (5 - g);
        int xc   = 12 * xcls + r;
        scx[tid]  = g_ss[xc];
        Bc[tid]   = g_ss[72 + xc];
        offc[tid] = xc * 36;
    }
    if (tid < TB * 6) mlsh[tid] = g_mult[b0 * 6 + tid];
    __syncthreads();

    for (int i = tid; i < TB * 72; i += BT) {
        int s = i / 72;
        int c = i - s * 72;
        int g = c / 12;
        int xcls = (g == 0 || g == 5) ? g : (5 - g);
        Asl[i] = scx[c] * mlsh[s * 6 + xcls];
    }
    __syncthreads();

    // build hp (bf16 pairs): writer (s, m) owns slots (2m, 2m+1) = h (2m-1, 2m)
    // m=0 lo slot and m=17 hi slot are the zero pads.
    for (int i = tid; i < TB * 18; i += BT) {
        int s = i / 18;
        int m = i - s * 18;
        const float* xr = x + (size_t)(b0 + s) * SAMP + 2 * m - 1;
        const float* As = Asl + s * 72;
        __nv_bfloat16* hb = hp + s * 2592 + 2 * m;
        #pragma unroll 4
        for (int c = 0; c < 72; c++) {
            float ha = 0.f, hb2 = 0.f;
            if (m > 0) {
                float va = xr[c * HH];
                ha = fmaxf(fmaf(As[c], va, Bc[c]), 0.f);
            }
            if (m < 17) {
                float vb = xr[c * HH + 1];
                hb2 = fmaxf(fmaf(As[c], vb, Bc[c]), 0.f);
            }
            *(__nv_bfloat162*)(hb + offc[c]) = __floats2bfloat162_rn(ha, hb2);
        }
    }
    __syncthreads();

    // conv: thread = (s, j), h0 = 2j; 12 FFMA2 chains (6 oc-pairs x 2 h)
    const int s = tid / 17;
    const int j = tid - s * 17;

    unsigned long long accA[6], accB[6];
    #pragma unroll
    for (int p = 0; p < 6; p++) { accA[p] = 0ULL; accB[p] = 0ULL; }

    const unsigned int* hprow = (const unsigned int*)(hp + s * 2592) + j;
    const ulonglong2*   w16   = (const ulonglong2*)wsm;

    #pragma unroll 4
    for (int ic = 0; ic < 72; ic++) {
        unsigned int u0 = hprow[ic * 18];       // slots (h0, h0+1)
        unsigned int u1 = hprow[ic * 18 + 1];   // slots (h0+2, h0+3)
        float v0 = __uint_as_float(u0 << 16);
        float v1 = __uint_as_float(u0 & 0xffff0000u);
        float v2 = __uint_as_float(u1 << 16);
        float v3 = __uint_as_float(u1 & 0xffff0000u);
        unsigned long long vp[4];
        PACK2(vp[0], v0);
        PACK2(vp[1], v1);
        PACK2(vp[2], v2);
        PACK2(vp[3], v3);
        const ulonglong2* wr = w16 + ic * 9;
        #pragma unroll
        for (int t = 0; t < 9; t++) {
            ulonglong2 ww = wr[t];
            const int k = t / 3;        // tap
            const int q = t % 3;        // oc quad
            FMA2(accA[2*q],     ww.x, vp[k],     accA[2*q]);
            FMA2(accA[2*q + 1], ww.y, vp[k],     accA[2*q + 1]);
            FMA2(accB[2*q],     ww.x, vp[k + 1], accB[2*q]);
            FMA2(accB[2*q + 1], ww.y, vp[k + 1], accB[2*q + 1]);
        }
    }

    // store: oc = 2p (lo halves) and 2p+1 (hi halves), h = (h0, h0+1) as float2
    float* ob = out + (size_t)(b0 + s) * OSAMP + 72 * HH + 2 * j;
    #pragma unroll
    for (int p = 0; p < 6; p++) {
        float alo, ahi, blo, bhi;
        UNPACK2(alo, ahi, accA[p]);
        UNPACK2(blo, bhi, accB[p]);
        float2 e0 = make_float2(alo, blo);
        float2 e1 = make_float2(ahi, bhi);
        *(float2*)(ob + (2*p)     * HH) = e0;
        *(float2*)(ob + (2*p + 1) * HH) = e1;
    }
}

// ---------------------------------------------------------------------------
extern "C" void kernel_launch(void* const* d_in, const int* in_sizes, int n_in,
                              void* d_out, int out_size)
{
    const float* x      = (const float*)d_in[0];
    const float* gamma  = (const float*)d_in[1];
    const float* beta   = (const float*)d_in[2];
    const float* conv_w = (const float*)d_in[3];
    const float* fc_w   = (const float*)d_in[4];
    const float* fc_b   = (const float*)d_in[5];
    float* out = (float*)d_out;

    const int B = in_sizes[0] / SAMP;   // 16384

    // smem: wsm 10368 + hp 41472 + Asl 2304 + Bc 288 + offc 288 + scx 288 + mlsh 192
    const int smem_k3 = 10368 + TB*2592*2 + TB*72*4 + 288 + 288 + 288 + TB*6*4; // 55200
    cudaFuncSetAttribute(k3_conv, cudaFuncAttributeMaxDynamicSharedMemorySize, smem_k3);

    k1_stats<<<B, 128>>>(x, fc_w, fc_b, out);
    k2_reduce<<<RED_BLOCKS, 144>>>();
    k2b_final<<<1, 72>>>(gamma, beta);
    k3_conv<<<B / TB, BT, smem_k3>>>(x, conv_w, out);
}

// round 5
// speedup vs baseline: 1.7703x; 1.7703x over previous
#include <cuda_runtime.h>
#include <math.h>

#define BATCH   16384
#define CCH     72
#define HH      34
#define SAMP    (CCH*HH)      /* 2448 */
#define OUTC    84
#define OSAMP   (OUTC*HH)     /* 2856 */
#define TB      8             /* samples per conv block */
#define BT      288           /* conv block threads = TB*36 */
#define RED_BLOCKS 64
#define RED_PER    256
#define BN_COUNT   (16384.0f*34.0f)
#define BN_EPS_F   1e-5f

__device__ float g_mult[BATCH*6];
__device__ float g_part[BATCH*144];
__device__ float g_part2[RED_BLOCKS*144];
__device__ float g_ss[144];

__device__ __forceinline__ float sigmoidf_(float z) {
    return 1.0f / (1.0f + __expf(-z));
}

#define FMA2(d, a, b, c) \
    asm("fma.rn.f32x2 %0, %1, %2, %3;" : "=l"(d) : "l"(a), "l"(b), "l"(c))
#define ADD2(d, a, b) \
    asm("add.rn.f32x2 %0, %1, %2;" : "=l"(d) : "l"(a), "l"(b))
#define PACK2(p, v) do { unsigned int _b = __float_as_uint(v); \
    asm("mov.b64 %0, {%1, %1};" : "=l"(p) : "r"(_b)); } while (0)
#define UNPACK2(lo, hi, p) do { unsigned int _l, _h; \
    asm("mov.b64 {%0, %1}, %2;" : "=r"(_l), "=r"(_h) : "l"(p)); \
    lo = __uint_as_float(_l); hi = __uint_as_float(_h); } while (0)

// ---------------------------------------------------------------------------
// K1: per-sample gates + BN partial sums + copy x into output channels [0,72)
// ---------------------------------------------------------------------------
__global__ void __launch_bounds__(128) k1_stats(
    const float* __restrict__ x,
    const float* __restrict__ fcw,
    const float* __restrict__ fcb,
    float* __restrict__ out)
{
    __shared__ float xs[SAMP];
    __shared__ float ws[HH];
    __shared__ float s1[CCH], s2[CCH], sw[CCH];
    __shared__ float lin[6];

    const int b   = blockIdx.x;
    const int tid = threadIdx.x;

    const float4* xin4 = (const float4*)(x + (size_t)b * SAMP);
    float4*       out4 = (float4*)(out + (size_t)b * OSAMP);
    float4*       xs4  = (float4*)xs;
    #pragma unroll
    for (int i = tid; i < SAMP/4; i += 128) {
        float4 v = xin4[i];
        xs4[i]  = v;
        out4[i] = v;
    }
    if (tid < HH) ws[tid] = fcw[tid];
    __syncthreads();

    if (tid < CCH) {
        float a1 = 0.f, a2 = 0.f, aw = 0.f;
        const float* row = xs + tid * HH;
        #pragma unroll
        for (int h = 0; h < HH; h++) {
            float v = row[h];
            a1 += v; a2 += v * v; aw += v * ws[h];
        }
        s1[tid] = a1; s2[tid] = a2; sw[tid] = aw;
    }
    __syncthreads();

    if (tid < 6) {
        float s = 0.f;
        #pragma unroll
        for (int c = 0; c < 12; c++) s += sw[tid * 12 + c];
        lin[tid] = s * (1.0f/12.0f) + fcb[0];
    }
    __syncthreads();

    if (tid < CCH) {
        const int cls = tid / 12;
        float mult;
        if (cls == 0)       mult = sigmoidf_(lin[5] + lin[0]);
        else if (cls == 5)  mult = 1.0f;
        else                mult = sigmoidf_(lin[5 - cls] + lin[5]);
        int src;
        if (cls == 0 || cls == 5) src = tid;
        else                      src = tid + 12 * (5 - 2 * cls);

        g_part[(size_t)b * 144 + tid * 2 + 0] = mult * s1[src];
        g_part[(size_t)b * 144 + tid * 2 + 1] = mult * mult * s2[src];
        if ((tid % 12) == 0) g_mult[b * 6 + cls] = mult;
    }
}

// ---------------------------------------------------------------------------
// K2 / K2b: deterministic BN stat reduction
// ---------------------------------------------------------------------------
__global__ void __launch_bounds__(144) k2_reduce()
{
    const int t   = threadIdx.x;
    const int blk = blockIdx.x;
    float acc = 0.f;
    size_t base = (size_t)blk * RED_PER * 144 + t;
    #pragma unroll 8
    for (int i = 0; i < RED_PER; i++) acc += g_part[base + (size_t)i * 144];
    g_part2[blk * 144 + t] = acc;
}

__global__ void __launch_bounds__(72) k2b_final(
    const float* __restrict__ gamma,
    const float* __restrict__ beta)
{
    const int c = threadIdx.x;
    float s = 0.f, q = 0.f;
    #pragma unroll 8
    for (int i = 0; i < RED_BLOCKS; i++) {
        s += g_part2[i * 144 + 2 * c + 0];
        q += g_part2[i * 144 + 2 * c + 1];
    }
    const float inv = 1.0f / BN_COUNT;
    float mu    = s * inv;
    float var   = q * inv - mu * mu;
    float scale = gamma[c] * rsqrtf(var + BN_EPS_F);
    g_ss[c]      = scale;
    g_ss[72 + c] = beta[c] - mu * scale;
}

// ---------------------------------------------------------------------------
// K3: xxx -> BN -> relu (fp32 smem) -> 3-tap conv
// 288 threads = 8 samples x 36 slots (build) / 8 x 17 hpairs x 2 ic-halves (conv)
// FFMA2 over oc-pairs, 2 h per thread, ic split across lane pairs, shfl combine
// ---------------------------------------------------------------------------
__global__ void __launch_bounds__(BT, 2) k3_conv(
    const float* __restrict__ x,
    const float* __restrict__ convw,
    float* __restrict__ out)
{
    extern __shared__ float sm[];
    float* wsm  = sm;                    // 2592 weights [(ic*3+k)*12 + oc]
    float* hp   = wsm + 2592;            // TB*2592 padded relu'd xxx (xxx-chan order)
    float* Asl  = hp  + TB * 2592;       // TB*72 combined scale
    float* Bc   = Asl + TB * 72;         // 72 shift
    int*   offc = (int*)(Bc + 72);       // 72 dst offset (xc*36)
    float* scx  = (float*)(offc + 72);   // 72
    float* mlsh = scx + 72;              // TB*6

    const int tid = threadIdx.x;
    const int b0  = blockIdx.x * TB;

    // weights -> smem
    for (int i = tid; i < 2592; i += BT) {
        int oc = i % 12;
        int k  = (i / 12) % 3;
        int ic = i / 36;
        wsm[i] = convw[oc * 216 + ic * 3 + k];
    }
    if (tid < 72) {
        int g = tid / 12, r = tid - g * 12;
        int xcls = (g == 0 || g == 5) ? g : (5 - g);
        int xc   = 12 * xcls + r;
        scx[tid]  = g_ss[xc];
        Bc[tid]   = g_ss[72 + xc];
        offc[tid] = xc * 36;
    }
    if (tid < TB * 6) mlsh[tid] = g_mult[b0 * 6 + tid];
    __syncthreads();

    for (int i = tid; i < TB * 72; i += BT) {
        int s = i / 72;
        int c = i - s * 72;
        int g = c / 12;
        int xcls = (g == 0 || g == 5) ? g : (5 - g);
        Asl[i] = scx[c] * mlsh[s * 6 + xcls];
    }
    __syncthreads();

    // hp build: thread owns (sample sb, slot m in 0..35); pads written inline
    {
        const int sb = tid / 36;
        const int m  = tid - sb * 36;
        const bool interior = (m >= 1) && (m <= 34);
        const float* xr = x + (size_t)(b0 + sb) * SAMP + (m - 1);
        const float* As = Asl + sb * 72;
        float*       hb = hp + sb * 2592 + m;
        #pragma unroll 8
        for (int c = 0; c < 72; c++) {
            float hv = 0.f;
            if (interior) {
                float v = xr[c * HH];
                hv = fmaxf(fmaf(As[c], v, Bc[c]), 0.f);
            }
            hb[offc[c]] = hv;
        }
    }
    __syncthreads();

    // conv: threads 0..271; thread = (s, j, e); h outputs 2j, 2j+1; ic in [36e, 36e+36)
    if (tid < 272) {
        const int pidx = tid >> 1;
        const int e    = tid & 1;
        const int s    = pidx / 17;
        const int j    = pidx - s * 17;

        unsigned long long accA[6], accB[6];
        #pragma unroll
        for (int p = 0; p < 6; p++) { accA[p] = 0ULL; accB[p] = 0ULL; }

        const float*      hrow = hp + s * 2592 + e * 36 * 36 + 2 * j;
        const ulonglong2* w16  = (const ulonglong2*)wsm + (size_t)e * 36 * 9;

        #pragma unroll 6
        for (int ic = 0; ic < 36; ic++) {
            float2 p01 = *(const float2*)(hrow + ic * 36);      // slots 2j, 2j+1
            float2 p23 = *(const float2*)(hrow + ic * 36 + 2);  // slots 2j+2, 2j+3
            unsigned long long vp[4];
            PACK2(vp[0], p01.x);
            PACK2(vp[1], p01.y);
            PACK2(vp[2], p23.x);
            PACK2(vp[3], p23.y);
            const ulonglong2* wr = w16 + ic * 9;
            #pragma unroll
            for (int t = 0; t < 9; t++) {
                ulonglong2 ww = wr[t];
                const int k = t / 3;        // tap
                const int q = t % 3;        // oc quad
                FMA2(accA[2*q],     ww.x, vp[k],     accA[2*q]);
                FMA2(accA[2*q + 1], ww.y, vp[k],     accA[2*q + 1]);
                FMA2(accB[2*q],     ww.x, vp[k + 1], accB[2*q]);
                FMA2(accB[2*q + 1], ww.y, vp[k + 1], accB[2*q + 1]);
            }
        }

        // combine ic-halves across the lane pair; lane e stores h = 2j + e
        const unsigned mask = (tid < 256) ? 0xFFFFFFFFu : 0x0000FFFFu;
        float* ob = out + (size_t)(b0 + s) * OSAMP + 72 * HH + 2 * j + e;
        #pragma unroll
        for (int p = 0; p < 6; p++) {
            unsigned long long send = e ? accA[p] : accB[p];
            unsigned long long mine = e ? accB[p] : accA[p];
            unsigned long long recv = __shfl_xor_sync(mask, send, 1);
            unsigned long long res;
            ADD2(res, mine, recv);
            float lo, hi;
            UNPACK2(lo, hi, res);
            ob[(2*p)     * HH] = lo;
            ob[(2*p + 1) * HH] = hi;
        }
    }
}

// ---------------------------------------------------------------------------
extern "C" void kernel_launch(void* const* d_in, const int* in_sizes, int n_in,
                              void* d_out, int out_size)
{
    const float* x      = (const float*)d_in[0];
    const float* gamma  = (const float*)d_in[1];
    const float* beta   = (const float*)d_in[2];
    const float* conv_w = (const float*)d_in[3];
    const float* fc_w   = (const float*)d_in[4];
    const float* fc_b   = (const float*)d_in[5];
    float* out = (float*)d_out;

    const int B = in_sizes[0] / SAMP;   // 16384

    // wsm 10368 + hp 82944 + Asl 2304 + Bc 288 + offc 288 + scx 288 + mlsh 192
    const int smem_k3 = 10368 + TB*2592*4 + TB*72*4 + 288 + 288 + 288 + TB*6*4; // 96672
    cudaFuncSetAttribute(k3_conv, cudaFuncAttributeMaxDynamicSharedMemorySize, smem_k3);

    k1_stats<<<B, 128>>>(x, fc_w, fc_b, out);
    k2_reduce<<<RED_BLOCKS, 144>>>();
    k2b_final<<<1, 72>>>(gamma, beta);
    k3_conv<<<B / TB, BT, smem_k3>>>(x, conv_w, out);
}